// round 7
// baseline (speedup 1.0000x reference)
#include <cuda_runtime.h>
#include <cuda_bf16.h>
#include <math.h>

#define N_NODES 100000
#define N_EDGES 600000
#define IN_DIM  6
#define HID     128
#define EPS     1e-5f

// ---------------- device scratch (allocation-free: __device__ globals) ------
__device__ float g_deg[N_NODES];
__device__ float g_inv[N_NODES];
__device__ float g_agg0[N_NODES * IN_DIM];
__device__ float g_h0[N_NODES * HID];     // layer0 pre-BN (normalized on the fly by consumers)
__device__ float g_agg1[N_NODES * HID];
__device__ float g_h1[N_NODES * HID];     // layer1 pre-BN
__device__ float g_p[N_NODES];
__device__ float g_r[N_NODES];
__device__ float g_aggs[N_NODES];
__device__ float g_bnstat[2 * HID];       // [0:128] sum, [128:256] sumsq
__device__ float g_scale[HID];
__device__ float g_shift[HID];
__device__ float g_wT[2 * HID * HID];     // concat-transposed [256][128] weights for layer1
__device__ int   g_is64;

// ---------------- helpers ---------------------------------------------------
// Detect int64 vs int32 edge_index: int64 values < 2^31 have all-zero high words.
// (Benign race on 'any': all writers store 1.)
__global__ void detect64_kernel(const unsigned int* e) {
    __shared__ int any;
    if (threadIdx.x == 0) any = 0;
    __syncthreads();
    for (int i = 1 + 2 * threadIdx.x; i < 4096; i += 2 * blockDim.x)
        if (e[i] != 0u) any = 1;
    __syncthreads();
    if (threadIdx.x == 0) g_is64 = any ? 0 : 1;
}

__device__ __forceinline__ void get_edge(const void* ei, int e, int E, int& src, int& dst) {
    if (g_is64) {
        const long long* p = (const long long*)ei;
        src = (int)p[e]; dst = (int)p[E + e];
    } else {
        const int* p = (const int*)ei;
        src = p[e]; dst = p[E + e];
    }
}

// ---------------- layer 0 ----------------------------------------------------
// degree + 6-dim feature scatter. Row stride 24B is 8-aligned -> three float2 REDs.
__global__ void edge0_kernel(const void* ei, const float* __restrict__ x, int E) {
    int e = blockIdx.x * blockDim.x + threadIdx.x;
    if (e >= E) return;
    int src, dst;
    get_edge(ei, e, E, src, dst);
    atomicAdd(&g_deg[dst], 1.f);
    const float2* xs = (const float2*)(x + (size_t)src * IN_DIM);
    float2* ag = (float2*)(g_agg0 + (size_t)dst * IN_DIM);
    float2 v0 = xs[0], v1 = xs[1], v2 = xs[2];
    atomicAdd(&ag[0], v0);
    atomicAdd(&ag[1], v1);
    atomicAdd(&ag[2], v2);
}

// h0_pre[n][j] = (agg0[n]*inv) . w_l0[j] + b_l0[j] + x[n] . w_r0[j]
// Also writes g_inv and accumulates BN stats (sum, sumsq) per column (fused).
__global__ void __launch_bounds__(HID) linear0_kernel(
    const float* __restrict__ x,
    const float* __restrict__ wl, const float* __restrict__ bl,
    const float* __restrict__ wr, int n)
{
    __shared__ float xs[HID * IN_DIM];
    __shared__ float as[HID * IN_DIM];
    __shared__ float invs[HID];
    int j = threadIdx.x;
    int base = blockIdx.x * HID;

    for (int idx = j; idx < HID * IN_DIM; idx += HID) {
        int g = base * IN_DIM + idx;
        bool ok = (g < n * IN_DIM);
        xs[idx] = ok ? x[g] : 0.f;
        as[idx] = ok ? g_agg0[g] : 0.f;
    }
    {
        int node = base + j;
        float iv = 0.f;
        if (node < n) {
            float d = g_deg[node];
            iv = 1.f / fmaxf(d, 1.f);
            g_inv[node] = iv;
        }
        invs[j] = iv;
    }
    __syncthreads();

    float WL[IN_DIM], WR[IN_DIM];
#pragma unroll
    for (int d = 0; d < IN_DIM; d++) { WL[d] = wl[j * IN_DIM + d]; WR[d] = wr[j * IN_DIM + d]; }
    float bj = bl[j];

    int nn = min(HID, n - base);
    float s = 0.f, q = 0.f;
    for (int m = 0; m < nn; m++) {
        float iv = invs[m];
        float acc = bj;
#pragma unroll
        for (int d = 0; d < IN_DIM; d++)
            acc += as[m * IN_DIM + d] * iv * WL[d] + xs[m * IN_DIM + d] * WR[d];
        g_h0[(size_t)(base + m) * HID + j] = acc;
        s += acc; q += acc * acc;
    }
    atomicAdd(&g_bnstat[j], s);
    atomicAdd(&g_bnstat[HID + j], q);
}

// ---------------- batch norm -------------------------------------------------
// Consumes g_bnstat into scale/shift, then re-zeroes stats for the next layer.
__global__ void bnfinal_kernel(const float* __restrict__ gamma,
                               const float* __restrict__ beta, float inv_n) {
    int j = threadIdx.x;
    float mean = g_bnstat[j] * inv_n;
    float var = fmaxf(g_bnstat[HID + j] * inv_n - mean * mean, 0.f);
    float sc = gamma[j] * rsqrtf(var + EPS);
    g_scale[j] = sc;
    g_shift[j] = beta[j] - mean * sc;
    g_bnstat[j] = 0.f;
    g_bnstat[HID + j] = 0.f;
}

// ---------------- layer 1 ----------------------------------------------------
// warp per edge, float4 vector atomics (sm_90+). BN+relu of h0 applied on the fly
// (g_scale/g_shift hold layer-0 values at this point).
__global__ void __launch_bounds__(256) edge1_kernel(const void* ei, int E) {
    int ew = (blockIdx.x * blockDim.x + threadIdx.x) >> 5;
    int lane = threadIdx.x & 31;
    if (ew >= E) return;
    int src, dst;
    get_edge(ei, ew, E, src, dst);
    int c = lane * 4;
    float4 v = *(const float4*)(g_h0 + (size_t)src * HID + c);
    float4 sc = *(const float4*)(g_scale + c);
    float4 sh = *(const float4*)(g_shift + c);
    v.x = fmaxf(v.x * sc.x + sh.x, 0.f);
    v.y = fmaxf(v.y * sc.y + sh.y, 0.f);
    v.z = fmaxf(v.z * sc.z + sh.z, 0.f);
    v.w = fmaxf(v.w * sc.w + sh.w, 0.f);
    atomicAdd((float4*)(g_agg1 + (size_t)dst * HID + c), v);
}

// build transposed concat weight wT[k][j]: k<128 -> w_l1[j][k], else w_r1[j][k-128]
__global__ void prepw_kernel(const float* __restrict__ wl, const float* __restrict__ wr) {
    int idx = blockIdx.x * blockDim.x + threadIdx.x;
    if (idx >= 2 * HID * HID) return;
    int k = idx / HID, j = idx % HID;
    g_wT[idx] = (k < HID) ? wl[j * HID + k] : wr[j * HID + (k - HID)];
}

// [N x 256] @ [256 x 128] register-tiled SIMT GEMM; A = [agg1*inv | bnrelu(h0)]
// Thread (tx,ty) handles rows i*16+ty, cols j*16+tx -> all LDS conflict-free,
// stores coalesced. BN stats for h1 are accumulated in the epilogue (fused).
__global__ void __launch_bounds__(256) gemm1_kernel(const float* __restrict__ bias, int n) {
    __shared__ float As[128][16];
    __shared__ float Bs[16][128];
    __shared__ float shs[8][128];
    __shared__ float shq[8][128];
    int tid = threadIdx.x;
    int tx = tid & 15, ty = tid >> 4;
    int row0 = blockIdx.x * 128;
    float acc[8][8];
#pragma unroll
    for (int i = 0; i < 8; i++)
#pragma unroll
        for (int j = 0; j < 8; j++) acc[i][j] = 0.f;

    for (int kt = 0; kt < 16; kt++) {
        const float* a = (kt < 8) ? g_agg1 : g_h0;
        int kc = (kt & 7) << 4;
        // A tile: 128 rows x 16 cols; 256 threads x 2 float4
#pragma unroll
        for (int r = 0; r < 2; r++) {
            int f = tid * 2 + r;
            int m = f >> 2, q = (f & 3) << 2;
            int gm = row0 + m;
            float4 v = make_float4(0.f, 0.f, 0.f, 0.f);
            if (gm < n) {
                v = *(const float4*)(a + (size_t)gm * HID + kc + q);
                if (kt < 8) {
                    float s = g_inv[gm];
                    v.x *= s; v.y *= s; v.z *= s; v.w *= s;
                } else {
                    // bn+relu of h0 on the fly (layer-0 scale/shift still live)
                    float4 sc = *(const float4*)(g_scale + kc + q);
                    float4 sh = *(const float4*)(g_shift + kc + q);
                    v.x = fmaxf(v.x * sc.x + sh.x, 0.f);
                    v.y = fmaxf(v.y * sc.y + sh.y, 0.f);
                    v.z = fmaxf(v.z * sc.z + sh.z, 0.f);
                    v.w = fmaxf(v.w * sc.w + sh.w, 0.f);
                }
            }
            *(float4*)&As[m][q] = v;
        }
        // B tile: 16 rows x 128 cols (already transposed in g_wT)
#pragma unroll
        for (int r = 0; r < 2; r++) {
            int f = tid * 2 + r;
            int k = f >> 5, jq = (f & 31) << 2;
            *(float4*)&Bs[k][jq] = *(const float4*)(g_wT + (size_t)(kt * 16 + k) * HID + jq);
        }
        __syncthreads();
#pragma unroll
        for (int k = 0; k < 16; k++) {
            float ra[8], rb[8];
#pragma unroll
            for (int i = 0; i < 8; i++) ra[i] = As[i * 16 + ty][k];     // 2 addrs, banks k / k+16
#pragma unroll
            for (int j = 0; j < 8; j++) rb[j] = Bs[k][j * 16 + tx];     // 16 consecutive banks
#pragma unroll
            for (int i = 0; i < 8; i++)
#pragma unroll
                for (int j = 0; j < 8; j++) acc[i][j] += ra[i] * rb[j];
        }
        __syncthreads();
    }
    // ---- epilogue: store h1 + accumulate per-column BN stats
    float bj[8];
#pragma unroll
    for (int j = 0; j < 8; j++) bj[j] = bias[j * 16 + tx];
    float cs[8], cq[8];
#pragma unroll
    for (int j = 0; j < 8; j++) { cs[j] = 0.f; cq[j] = 0.f; }
#pragma unroll
    for (int i = 0; i < 8; i++) {
        int gm = row0 + i * 16 + ty;
        if (gm >= n) continue;
        float* orow = g_h1 + (size_t)gm * HID;
#pragma unroll
        for (int j = 0; j < 8; j++) {
            float v = acc[i][j] + bj[j];
            orow[j * 16 + tx] = v;                   // lanes 0-15 consecutive: coalesced
            cs[j] += v; cq[j] += v * v;
        }
    }
    // combine the two ty values sharing a warp (lane ^ 16 has same tx)
#pragma unroll
    for (int j = 0; j < 8; j++) {
        cs[j] += __shfl_xor_sync(0xffffffffu, cs[j], 16);
        cq[j] += __shfl_xor_sync(0xffffffffu, cq[j], 16);
    }
    int w = tid >> 5, lx = tid & 15;
    if ((tid & 16) == 0) {
#pragma unroll
        for (int j = 0; j < 8; j++) {
            shs[w][j * 16 + lx] = cs[j];
            shq[w][j * 16 + lx] = cq[j];
        }
    }
    __syncthreads();
    if (tid < HID) {
        float s = 0.f, q = 0.f;
#pragma unroll
        for (int w2 = 0; w2 < 8; w2++) { s += shs[w2][tid]; q += shq[w2][tid]; }
        atomicAdd(&g_bnstat[tid], s);
        atomicAdd(&g_bnstat[HID + tid], q);
    }
}

// warp per node: BN+relu on h1 (register-only), and p = h1.w_l2, r = h1.w_r2
__global__ void __launch_bounds__(256) apply1_kernel(
    const float* __restrict__ wl2, const float* __restrict__ wr2, int n)
{
    int node = (blockIdx.x * blockDim.x + threadIdx.x) >> 5;
    int lane = threadIdx.x & 31;
    if (node >= n) return;
    int c = lane * 4;
    float4 v = *(float4*)(g_h1 + (size_t)node * HID + c);
    float4 sc = *(const float4*)(g_scale + c);
    float4 sh = *(const float4*)(g_shift + c);
    v.x = fmaxf(v.x * sc.x + sh.x, 0.f);
    v.y = fmaxf(v.y * sc.y + sh.y, 0.f);
    v.z = fmaxf(v.z * sc.z + sh.z, 0.f);
    v.w = fmaxf(v.w * sc.w + sh.w, 0.f);
    float4 a = *(const float4*)(wl2 + c);
    float4 b = *(const float4*)(wr2 + c);
    float pp = v.x * a.x + v.y * a.y + v.z * a.z + v.w * a.w;
    float rr = v.x * b.x + v.y * b.y + v.z * b.z + v.w * b.w;
#pragma unroll
    for (int o = 16; o; o >>= 1) {
        pp += __shfl_xor_sync(0xffffffffu, pp, o);
        rr += __shfl_xor_sync(0xffffffffu, rr, o);
    }
    if (lane == 0) { g_p[node] = pp; g_r[node] = rr; }
}

// ---------------- layer 2 ----------------------------------------------------
__global__ void edge2_kernel(const void* ei, int E) {
    int e = blockIdx.x * blockDim.x + threadIdx.x;
    if (e >= E) return;
    int src, dst;
    get_edge(ei, e, E, src, dst);
    atomicAdd(&g_aggs[dst], g_p[src]);
}

__global__ void final_kernel(const float* __restrict__ bl2, float* __restrict__ out, int n) {
    int i = blockIdx.x * blockDim.x + threadIdx.x;
    if (i >= n) return;
    float z = g_aggs[i] * g_inv[i] + bl2[0] + g_r[i];
    out[i] = 1.f / (1.f + expf(-z));
}

// ---------------- launch -----------------------------------------------------
extern "C" void kernel_launch(void* const* d_in, const int* in_sizes, int n_in,
                              void* d_out, int out_size)
{
    const float* x    = (const float*)d_in[0];
    const void*  ei   = d_in[1];
    const float* wl0  = (const float*)d_in[2];
    const float* bl0  = (const float*)d_in[3];
    const float* wr0  = (const float*)d_in[4];
    const float* bg0  = (const float*)d_in[5];
    const float* bb0  = (const float*)d_in[6];
    const float* wl1  = (const float*)d_in[7];
    const float* bl1  = (const float*)d_in[8];
    const float* wr1  = (const float*)d_in[9];
    const float* bg1  = (const float*)d_in[10];
    const float* bb1  = (const float*)d_in[11];
    const float* wl2  = (const float*)d_in[12];
    const float* bl2  = (const float*)d_in[13];
    const float* wr2  = (const float*)d_in[14];
    float* out = (float*)d_out;

    int n = in_sizes[0] / IN_DIM;       // 100000
    int E = in_sizes[1] / 2;            // 600000

    void* p_deg;   cudaGetSymbolAddress(&p_deg,   g_deg);
    void* p_agg0;  cudaGetSymbolAddress(&p_agg0,  g_agg0);
    void* p_agg1;  cudaGetSymbolAddress(&p_agg1,  g_agg1);
    void* p_aggs;  cudaGetSymbolAddress(&p_aggs,  g_aggs);
    void* p_bn;    cudaGetSymbolAddress(&p_bn,    g_bnstat);

    // dtype detect for edge_index
    detect64_kernel<<<1, 256>>>((const unsigned int*)ei);

    // zero accumulators (async memsets are graph-capturable)
    cudaMemsetAsync(p_deg,  0, (size_t)n * sizeof(float));
    cudaMemsetAsync(p_agg0, 0, (size_t)n * IN_DIM * sizeof(float));
    cudaMemsetAsync(p_agg1, 0, (size_t)n * HID * sizeof(float));
    cudaMemsetAsync(p_aggs, 0, (size_t)n * sizeof(float));
    cudaMemsetAsync(p_bn,   0, 2 * HID * sizeof(float));
    prepw_kernel<<<(2 * HID * HID + 255) / 256, 256>>>(wl1, wr1);

    float inv_n = 1.f / (float)n;

    // ---- layer 0 (stats fused into linear0; BN applied on the fly downstream)
    edge0_kernel<<<(E + 255) / 256, 256>>>(ei, x, E);
    linear0_kernel<<<(n + HID - 1) / HID, HID>>>(x, wl0, bl0, wr0, n);
    bnfinal_kernel<<<1, HID>>>(bg0, bb0, inv_n);   // consumes + re-zeroes stats

    // ---- layer 1 (stats fused into gemm1 epilogue)
    edge1_kernel<<<(E * 32 + 255) / 256, 256>>>(ei, E);
    gemm1_kernel<<<(n + 127) / 128, 256>>>(bl1, n);
    bnfinal_kernel<<<1, HID>>>(bg1, bb1, inv_n);   // consumes + re-zeroes stats
    apply1_kernel<<<(n * 32 + 255) / 256, 256>>>(wl2, wr2, n);

    // ---- layer 2
    edge2_kernel<<<(E + 255) / 256, 256>>>(ei, E);
    final_kernel<<<(n + 255) / 256, 256>>>(bl2, out, n);
}